// round 5
// baseline (speedup 1.0000x reference)
#include <cuda_runtime.h>
#include <cstdint>

#define KMIX 64
#define DDIM 16
#define KS2C 0x1BD11BF0u   // 0x1BD11BDA ^ 0 ^ 42

__device__ float g_logp[KMIX];
// rotation multipliers 2^r, r in {13,15,26,6,17,29,16,24}; kept in mutable
// global so ptxas cannot strength-reduce the multiplies back into shifts.
__device__ uint32_t g_mul[8] = {1u << 13, 1u << 15, 1u << 26, 1u << 6,
                                1u << 17, 1u << 29, 1u << 16, 1u << 24};

// --- logp precompute: p = pi/sum(pi); logits = log(p) ------------------------
__global__ void prep_logp(const float* __restrict__ pi) {
    __shared__ float s_sum;
    int k = threadIdx.x;
    if (k == 0) {
        float acc = 0.0f;
        for (int j = 0; j < KMIX; j++) acc += pi[j];
        s_sum = acc;
    }
    __syncthreads();
    if (k < KMIX) g_logp[k] = logf(pi[k] / s_sum);
}

// one threefry round: x0 += x1; x1 = rotl(x1,r) ^ x0
// rotl as two multiplies (IMAD + IMAD.HI, fma pipe) + LOP3 (a|b)^c (alu pipe).
// No inline asm: the C expression (lo|hi)^x0 compiles to a single LOP3.
__device__ __forceinline__ void tf_round(uint32_t& x0, uint32_t& x1, uint32_t m) {
    x0 += x1;
    uint32_t lo = x1 * m;
    uint32_t hi = __umulhi(x1, m);
    x1 = (lo | hi) ^ x0;
}

// key-injection (x0+=A, x1+=B) folded into the following round's IADD3
__device__ __forceinline__ void tf_round_inj(uint32_t& x0, uint32_t& x1,
                                             uint32_t A, uint32_t B, uint32_t m) {
    x1 += B;
    x0 = x0 + x1 + A;          // IADD3
    uint32_t lo = x1 * m;
    uint32_t hi = __umulhi(x1, m);
    x1 = (lo | hi) ^ x0;
}

// threefry2x32(key=(0,42), ctr=(0,i)), 20 rounds; bits = out0 ^ out1
__device__ __forceinline__ uint32_t rng_bits(
    uint32_t i,
    uint32_t m13, uint32_t m15, uint32_t m26, uint32_t m6,
    uint32_t m17, uint32_t m29, uint32_t m16, uint32_t m24) {
    uint32_t x0 = 0u, x1 = i + 42u;
    tf_round(x0, x1, m13); tf_round(x0, x1, m15);
    tf_round(x0, x1, m26); tf_round(x0, x1, m6);
    tf_round_inj(x0, x1, 42u, KS2C + 1u, m17);
    tf_round(x0, x1, m29); tf_round(x0, x1, m16); tf_round(x0, x1, m24);
    tf_round_inj(x0, x1, KS2C, 2u, m13);
    tf_round(x0, x1, m15); tf_round(x0, x1, m26); tf_round(x0, x1, m6);
    tf_round_inj(x0, x1, 0u, 45u, m17);
    tf_round(x0, x1, m29); tf_round(x0, x1, m16); tf_round(x0, x1, m24);
    tf_round_inj(x0, x1, 42u, KS2C + 4u, m13);
    tf_round(x0, x1, m15); tf_round(x0, x1, m26); tf_round(x0, x1, m6);
    return (x0 + KS2C) ^ (x1 + 5u);
}

#define NLN2 (-0.69314718055994530942f)
#define TINY 1.17549435e-38f

__device__ __forceinline__ float gumbel_exact(float u) {
    return -logf(-logf(u));        // accurate libdevice path (matches XLA)
}

// ----------------------------------------------------------------------------
// 1 warp = 2 samples. lanes 0..15 -> sample A, lanes 16..31 -> sample B.
// lane (g,p) owns components 4p..4p+3 of its sample.
// ----------------------------------------------------------------------------
__global__ __launch_bounds__(256)
void gmm_sample_kernel(const float* __restrict__ x,
                       const float* __restrict__ means,
                       const float* __restrict__ Ls,
                       float* __restrict__ y,
                       int nPairs) {
    __shared__ __align__(16) float s_logp[KMIX];
    if (threadIdx.x < KMIX) s_logp[threadIdx.x] = g_logp[threadIdx.x];
    // rotation multipliers into registers (mutable global -> no const-folding)
    uint32_t m13 = g_mul[0], m15 = g_mul[1], m26 = g_mul[2], m6 = g_mul[3];
    uint32_t m17 = g_mul[4], m29 = g_mul[5], m16 = g_mul[6], m24 = g_mul[7];
    __syncthreads();

    int warp = (blockIdx.x * blockDim.x + threadIdx.x) >> 5;
    int lane = threadIdx.x & 31;
    if (warp >= nPairs) return;

    int p = lane & 15;
    int g = lane >> 4;
    int n = 2 * warp + g;
    int kbase = 4 * p;

    float4 cv = *reinterpret_cast<const float4*>(&s_logp[kbase]);

    uint32_t ibase = (uint32_t)n * KMIX + (uint32_t)kbase;
    uint32_t b0 = rng_bits(ibase + 0u, m13, m15, m26, m6, m17, m29, m16, m24);
    uint32_t b1 = rng_bits(ibase + 1u, m13, m15, m26, m6, m17, m29, m16, m24);
    uint32_t b2 = rng_bits(ibase + 2u, m13, m15, m26, m6, m17, m29, m16, m24);
    uint32_t b3 = rng_bits(ibase + 3u, m13, m15, m26, m6, m17, m29, m16, m24);

    // bits -> uniform [tiny,1) -> fast gumbel (logit folded into final FFMA)
    float u0 = fmaxf(__uint_as_float((b0 >> 9) | 0x3f800000u) - 1.0f, TINY);
    float u1 = fmaxf(__uint_as_float((b1 >> 9) | 0x3f800000u) - 1.0f, TINY);
    float u2 = fmaxf(__uint_as_float((b2 >> 9) | 0x3f800000u) - 1.0f, TINY);
    float u3 = fmaxf(__uint_as_float((b3 >> 9) | 0x3f800000u) - 1.0f, TINY);

    float t0 = __log2f(u0) * NLN2;          // = -ln(u) > 0
    float t1 = __log2f(u1) * NLN2;
    float t2 = __log2f(u2) * NLN2;
    float t3 = __log2f(u3) * NLN2;

    float v0 = fmaf(__log2f(t0), NLN2, cv.x);
    float v1 = fmaf(__log2f(t1), NLN2, cv.y);
    float v2 = fmaf(__log2f(t2), NLN2, cv.z);
    float v3 = fmaf(__log2f(t3), NLN2, cv.w);

    // local top-2 over 4 (ties -> lower index) + local tmin
    float w1, w2; int j1;
    if (v0 >= v1) { w1 = v0; j1 = kbase;     w2 = v1; }
    else          { w1 = v1; j1 = kbase + 1; w2 = v0; }
    float s1, s2; int m1;
    if (v2 >= v3) { s1 = v2; m1 = kbase + 2; s2 = v3; }
    else          { s1 = v3; m1 = kbase + 3; s2 = v2; }
    if (s1 > w1) { w2 = fmaxf(w1, s2); w1 = s1; j1 = m1; }
    else         { w2 = fmaxf(w2, s1); }
    float tmin = fminf(fminf(t0, t1), fminf(t2, t3));

    // 16-lane butterfly top-2 + tmin (serves both samples simultaneously)
#pragma unroll
    for (int o = 1; o < 16; o <<= 1) {
        float ov1 = __shfl_xor_sync(0xffffffffu, w1, o);
        int   oj1 = __shfl_xor_sync(0xffffffffu, j1, o);
        float ov2 = __shfl_xor_sync(0xffffffffu, w2, o);
        float ot  = __shfl_xor_sync(0xffffffffu, tmin, o);
        tmin = fminf(tmin, ot);
        if (ov1 > w1 || (ov1 == w1 && oj1 < j1)) {
            w2 = fmaxf(w1, ov2); w1 = ov1; j1 = oj1;
        } else {
            w2 = fmaxf(w2, ov1);
        }
    }
    int z = j1;

    // rigorous fast-path error bound:
    //   per-value err <= ~1.65e-7/t (u->1 blowup) + ~3e-6*(1+|g|)
    // tmin bounds 1/t over all candidates; 3x+ safety on each term.
    float thr = __fdividef(1e-6f, tmin) + 2e-5f * fmaxf(1.0f, fabsf(w1)) + 2e-6f;
    bool need = (w1 - w2) <= thr;

    if (__any_sync(0xffffffffu, need)) {    // rare exact recompute
        float e0 = gumbel_exact(u0) + cv.x;
        float e1 = gumbel_exact(u1) + cv.y;
        float e2 = gumbel_exact(u2) + cv.z;
        float e3 = gumbel_exact(u3) + cv.w;
        float av; int ai;
        if (e0 >= e1) { av = e0; ai = kbase; } else { av = e1; ai = kbase + 1; }
        if (e2 > av) { av = e2; ai = kbase + 2; }
        if (e3 > av) { av = e3; ai = kbase + 3; }
#pragma unroll
        for (int o = 1; o < 16; o <<= 1) {
            float ov = __shfl_xor_sync(0xffffffffu, av, o);
            int   oi = __shfl_xor_sync(0xffffffffu, ai, o);
            if (ov > av || (ov == av && oi < ai)) { av = ov; ai = oi; }
        }
        if (need) z = ai;
    }

    // matvec: lane (g,p) computes y[n][p] = dot(x[n,:], L[z][:,p]) + means[z][p]
    float xv = x[(size_t)n * DDIM + p];
    float acc = __ldg(&means[z * DDIM + p]);
    const float* Lb = Ls + (size_t)z * (DDIM * DDIM) + p;
    int src0 = g << 4;
#pragma unroll
    for (int d = 0; d < DDIM; d++) {
        float xd = __shfl_sync(0xffffffffu, xv, src0 + d);
        acc = fmaf(xd, __ldg(Lb + d * DDIM), acc);
    }
    y[(size_t)n * DDIM + p] = acc;
}

// ----------------------------------------------------------------------------
extern "C" void kernel_launch(void* const* d_in, const int* in_sizes, int n_in,
                              void* d_out, int out_size) {
    const float* x     = (const float*)d_in[0];   // (N, 16)
    const float* pi    = (const float*)d_in[1];   // (64,)
    const float* means = (const float*)d_in[2];   // (64, 16)
    const float* Ls    = (const float*)d_in[3];   // (64, 16, 16)
    float* y = (float*)d_out;                     // (N, 16)

    int N = in_sizes[0] / DDIM;
    int nPairs = N / 2;                           // N = 1,000,000 (even)

    prep_logp<<<1, 64>>>(pi);

    const int threads = 256;                      // 8 warps = 16 samples / CTA
    int warpsPerBlock = threads / 32;
    int blocks = (nPairs + warpsPerBlock - 1) / warpsPerBlock;
    gmm_sample_kernel<<<blocks, threads>>>(x, means, Ls, y, nPairs);
}

// round 7
// speedup vs baseline: 1.1739x; 1.1739x over previous
#include <cuda_runtime.h>
#include <cstdint>

#define KMIX 64
#define DDIM 16
#define KS2C 0x1BD11BF0u   // 0x1BD11BDA ^ 0 ^ 42
#define NLN2 (-0.69314718055994530942f)
#define TINY 1.17549435e-38f

__device__ __align__(16) float g_logp[KMIX];
__device__ float4 g_Ltt4[KMIX * 64];   // [z][c(4)][p(16)] -> Ltt[z][c][p].j = L[z][4c+j][p]
// mutable constants: {2^15, 2^29, 2^6, 1, 2^23} — loaded at runtime so ptxas
// cannot strength-reduce the IMADs back into shifts / fold the add.
__device__ uint32_t g_c[5] = {1u << 15, 1u << 29, 1u << 6, 1u, 1u << 23};

// --- prep: logits + L transpose to [z][c][p][j] float4 layout ----------------
__global__ void prep_kernel(const float* __restrict__ pi,
                            const float* __restrict__ Ls) {
    int z = blockIdx.x, t = threadIdx.x;
    int c = t >> 6, rem = t & 63, p = rem >> 2, j = rem & 3;
    ((float*)g_Ltt4)[z * 256 + c * 64 + p * 4 + j] = Ls[z * 256 + (4 * c + j) * 16 + p];
    if (z == 0 && t < KMIX) {
        float acc = 0.0f;
        for (int q = 0; q < KMIX; q++) acc += pi[q];
        g_logp[t] = logf(pi[t] / acc);
    }
}

// A-round: add on fma pipe (IMAD via runtime 'one'), rotate = SHF (alu), xor = LOP3
__device__ __forceinline__ void tfA(uint32_t& x0, uint32_t& x1, int r, uint32_t one) {
    x0 = x1 * one + x0;
    x1 = __funnelshift_l(x1, x1, r) ^ x0;
}
// B-round: add + rotate all on fma pipe (IMAD, IMAD, IMAD.HI), xor = LOP3 (alu)
__device__ __forceinline__ void tfB(uint32_t& x0, uint32_t& x1, uint32_t m, uint32_t one) {
    x0 = x1 * one + x0;
    uint32_t lo = x1 * m;
    uint32_t hi = __umulhi(x1, m);
    x1 = (lo | hi) ^ x0;
}
// injection round (A-style): x1+=B on fma (IMAD imm), x0=x0+x1+A one IADD3
__device__ __forceinline__ void tfAinj(uint32_t& x0, uint32_t& x1,
                                       uint32_t A, uint32_t B, int r, uint32_t one) {
    x1 = x1 * one + B;
    x0 = x0 + x1 + A;
    x1 = __funnelshift_l(x1, x1, r) ^ x0;
}

// threefry2x32(key=(0,42), ctr=(0,i)), 20 rounds; bits = out0 ^ out1
__device__ __forceinline__ uint32_t rng_bits(uint32_t i, uint32_t m15, uint32_t m29,
                                             uint32_t m6, uint32_t one) {
    uint32_t x1 = i + 42u;
    uint32_t x0 = x1;                       // round 1 (x0 was 0): x0 += x1
    x1 = __funnelshift_l(x1, x1, 13) ^ x0;  //   rotate/xor of round 1
    tfB(x0, x1, m15, one);
    tfA(x0, x1, 26, one);
    tfB(x0, x1, m6, one);
    tfAinj(x0, x1, 42u, KS2C + 1u, 17, one);
    tfB(x0, x1, m29, one);
    tfA(x0, x1, 16, one);
    tfA(x0, x1, 24, one);
    tfAinj(x0, x1, KS2C, 2u, 13, one);
    tfB(x0, x1, m15, one);
    tfA(x0, x1, 26, one);
    tfB(x0, x1, m6, one);
    tfAinj(x0, x1, 0u, 45u, 17, one);
    tfB(x0, x1, m29, one);
    tfA(x0, x1, 16, one);
    tfA(x0, x1, 24, one);
    tfAinj(x0, x1, 42u, KS2C + 4u, 13, one);
    tfB(x0, x1, m15, one);
    tfA(x0, x1, 26, one);
    tfA(x0, x1, 6, one);
    return (x0 + KS2C) ^ (x1 + 5u);
}

__device__ __forceinline__ float gumbel_exact(float u) {
    return -logf(-logf(u));   // accurate libdevice path (matches XLA)
}

// monotone float->uint map (order-preserving, finite inputs)
__device__ __forceinline__ uint32_t f2mono(float v) {
    uint32_t s = __float_as_uint(v);
    return s ^ ((uint32_t)((int32_t)s >> 31) | 0x80000000u);
}
// inverse map
__device__ __forceinline__ float mono2f(uint32_t m) {
    uint32_t s = m ^ ((uint32_t)((int32_t)(~m) >> 31) | 0x80000000u);
    return __uint_as_float(s);
}

// ----------------------------------------------------------------------------
// 1 warp = 2 samples. lanes 0..15 -> sample A, lanes 16..31 -> sample B.
// lane (g,p) owns components 4p..4p+3 of its sample.
// ----------------------------------------------------------------------------
__global__ __launch_bounds__(256, 4)
void gmm_sample_kernel(const float* __restrict__ x,
                       const float* __restrict__ means,
                       float* __restrict__ y,
                       int nPairs) {
    __shared__ float4 s_x4[8][8];          // [warpInBlock][2 samples x 4 chunks]

    uint32_t m15 = g_c[0], m29 = g_c[1], m6 = g_c[2], one = g_c[3], m23 = g_c[4];

    int warp = (blockIdx.x * blockDim.x + threadIdx.x) >> 5;
    int lane = threadIdx.x & 31;
    int wib  = (threadIdx.x >> 5);
    if (warp >= nPairs) return;

    int p = lane & 15;
    int g = lane >> 4;
    int n = 2 * warp + g;
    int kbase = 4 * p;

    float4 cv = __ldg(&((const float4*)g_logp)[p]);

    uint32_t ibase = (uint32_t)n * KMIX + (uint32_t)kbase;
    uint32_t b0 = rng_bits(ibase + 0u, m15, m29, m6, one);
    uint32_t b1 = rng_bits(ibase + 1u, m15, m29, m6, one);
    uint32_t b2 = rng_bits(ibase + 2u, m15, m29, m6, one);
    uint32_t b3 = rng_bits(ibase + 3u, m15, m29, m6, one);

    // bits -> uniform [tiny,1): b>>9 done as umulhi(b, 2^23) on the fma pipe
    float u0 = fmaxf(__uint_as_float(__umulhi(b0, m23) | 0x3f800000u) - 1.0f, TINY);
    float u1 = fmaxf(__uint_as_float(__umulhi(b1, m23) | 0x3f800000u) - 1.0f, TINY);
    float u2 = fmaxf(__uint_as_float(__umulhi(b2, m23) | 0x3f800000u) - 1.0f, TINY);
    float u3 = fmaxf(__uint_as_float(__umulhi(b3, m23) | 0x3f800000u) - 1.0f, TINY);

    float t0 = __log2f(u0) * NLN2;         // = -ln(u) > 0
    float t1 = __log2f(u1) * NLN2;
    float t2 = __log2f(u2) * NLN2;
    float t3 = __log2f(u3) * NLN2;

    float v0 = fmaf(__log2f(t0), NLN2, cv.x);
    float v1 = fmaf(__log2f(t1), NLN2, cv.y);
    float v2 = fmaf(__log2f(t2), NLN2, cv.z);
    float v3 = fmaf(__log2f(t3), NLN2, cv.w);

    // pack: monotone uint key with (63 - k) in the low 6 bits (tie -> lower k wins)
    uint32_t pk0 = (f2mono(v0) & 0xFFFFFFC0u) | (uint32_t)(63 - kbase);
    uint32_t pk1 = (f2mono(v1) & 0xFFFFFFC0u) | (uint32_t)(62 - kbase);
    uint32_t pk2 = (f2mono(v2) & 0xFFFFFFC0u) | (uint32_t)(61 - kbase);
    uint32_t pk3 = (f2mono(v3) & 0xFFFFFFC0u) | (uint32_t)(60 - kbase);

    // local top-2 of 4 (pure IMNMX)
    uint32_t a  = max(pk0, pk1), bq = min(pk0, pk1);
    uint32_t cq = max(pk2, pk3), dq = min(pk2, pk3);
    uint32_t w1 = max(a, cq);
    uint32_t w2 = max(min(a, cq), max(bq, dq));
    float tmin = fminf(fminf(t0, t1), fminf(t2, t3));

    // 16-lane butterfly top-2 + tmin (both samples reduce simultaneously)
#pragma unroll
    for (int o = 1; o < 16; o <<= 1) {
        uint32_t o1 = __shfl_xor_sync(0xffffffffu, w1, o);
        uint32_t o2 = __shfl_xor_sync(0xffffffffu, w2, o);
        float    ot = __shfl_xor_sync(0xffffffffu, tmin, o);
        w2 = max(min(w1, o1), max(w2, o2));
        w1 = max(w1, o1);
        tmin = fminf(tmin, ot);
    }
    int z = 63 - (int)(w1 & 63u);

    // threshold: fast-log error (1e-6/t blowup + relative term) + 63-ulp packing slack
    float v1f = mono2f(w1);
    float v2f = mono2f(w2 & 0xFFFFFFC0u);
    float thr = __fdividef(1e-6f, tmin) + 6e-5f * fmaxf(1.0f, fabsf(v1f)) + 4e-6f;
    bool need = (v1f - v2f) <= thr;

    if (__any_sync(0xffffffffu, need)) {   // rare exact recompute
        float e0 = gumbel_exact(u0) + cv.x;
        float e1 = gumbel_exact(u1) + cv.y;
        float e2 = gumbel_exact(u2) + cv.z;
        float e3 = gumbel_exact(u3) + cv.w;
        float av; int ai;
        if (e0 >= e1) { av = e0; ai = kbase; } else { av = e1; ai = kbase + 1; }
        if (e2 > av) { av = e2; ai = kbase + 2; }
        if (e3 > av) { av = e3; ai = kbase + 3; }
#pragma unroll
        for (int o = 1; o < 16; o <<= 1) {
            float ov = __shfl_xor_sync(0xffffffffu, av, o);
            int   oi = __shfl_xor_sync(0xffffffffu, ai, o);
            if (ov > av || (ov == av && oi < ai)) { av = ov; ai = oi; }
        }
        if (need) z = ai;
    }

    // matvec via smem x-broadcast + transposed-L float4 loads:
    //   y[n][p] = means[z][p] + sum_c dot(x[n][4c..4c+3], Ltt[z][c][p])
    float xv = x[(size_t)n * DDIM + p];
    ((float*)&s_x4[wib][0])[lane] = xv;
    __syncwarp();

    float acc = __ldg(&means[z * DDIM + p]);
    const float4* Lt = &g_Ltt4[z * 64 + p];
    const float4* sx = &s_x4[wib][g * 4];
#pragma unroll
    for (int c = 0; c < 4; c++) {
        float4 xc = sx[c];                 // broadcast LDS.128
        float4 lc = __ldg(&Lt[c * 16]);    // coalesced LDG.128 (L1-resident table)
        acc = fmaf(xc.x, lc.x, acc);
        acc = fmaf(xc.y, lc.y, acc);
        acc = fmaf(xc.z, lc.z, acc);
        acc = fmaf(xc.w, lc.w, acc);
    }
    y[(size_t)n * DDIM + p] = acc;
}

// ----------------------------------------------------------------------------
extern "C" void kernel_launch(void* const* d_in, const int* in_sizes, int n_in,
                              void* d_out, int out_size) {
    const float* x     = (const float*)d_in[0];   // (N, 16)
    const float* pi    = (const float*)d_in[1];   // (64,)
    const float* means = (const float*)d_in[2];   // (64, 16)
    const float* Ls    = (const float*)d_in[3];   // (64, 16, 16)
    float* y = (float*)d_out;                     // (N, 16)

    int N = in_sizes[0] / DDIM;
    int nPairs = N / 2;                           // N = 1,000,000 (even)

    prep_kernel<<<KMIX, 256>>>(pi, Ls);

    const int threads = 256;                      // 8 warps = 16 samples / CTA
    int warpsPerBlock = threads / 32;
    int blocks = (nPairs + warpsPerBlock - 1) / warpsPerBlock;
    gmm_sample_kernel<<<blocks, threads>>>(x, means, y, nPairs);
}